// round 16
// baseline (speedup 1.0000x reference)
#include <cuda_runtime.h>
#include <mma.h>
#include <math.h>
#include <cstdint>

using namespace nvcuda;

#define BB 64
#define SS 1024
#define HH 1024
#define GG 4096
#define OO 128
#define NB 128
#define VV 32000

// Scratch (allocation-free rule: __device__ globals)
__device__ float g_gatesx[(size_t)SS * BB * GG];  // [S][B][4H], 1 GiB
__device__ float g_embT[(size_t)VV * HH];         // tf32-RN preconverted emb
__device__ float g_wihT[(size_t)GG * HH];         // tf32-RN preconverted W_ih
__device__ float g_h[2][BB * HH];                 // double-buffered hidden state
__device__ unsigned g_bar;                        // cumulative grid-barrier counter

// ---------------------------------------------------------------------------
__global__ void preconvert(const float* __restrict__ emb,
                           const float* __restrict__ Wih) {
    size_t i0 = (size_t)blockIdx.x * blockDim.x + threadIdx.x;
    size_t stride = (size_t)gridDim.x * blockDim.x;
    for (size_t k = i0; k < (size_t)VV * HH; k += stride)
        g_embT[k] = wmma::__float_to_tf32(emb[k]);
    for (size_t k = i0; k < (size_t)GG * HH; k += stride)
        g_wihT[k] = wmma::__float_to_tf32(Wih[k]);
}

// ---------------------------------------------------------------------------
// Phase A (unchanged from R14): 128x128x32 tiles, cp.async 2-stage, 2 CTA/SM
// ---------------------------------------------------------------------------
#define GX_TS   36
#define GX_TILE (128 * GX_TS)
#define GX_STG  (2 * GX_TILE)
#define SMEM_GX (2 * GX_STG * 4)

__device__ __forceinline__ void gx_stage(unsigned int sgb,
                                         const float* __restrict__ arow,
                                         const float* __restrict__ brow,
                                         int r, int hf, int kt) {
    unsigned int abase = sgb + (unsigned int)((kt & 1) * GX_STG + r * GX_TS + hf) * 4u;
    unsigned int bbase = abase + (unsigned int)GX_TILE * 4u;
    const float* asrc = arow + kt * 32 + hf;
    const float* bsrc = brow + kt * 32 + hf;
    #pragma unroll
    for (int i = 0; i < 4; i++) {
        asm volatile("cp.async.cg.shared.global [%0], [%1], 16;"
                     :: "r"(abase + 16u * i), "l"(asrc + 4 * i));
        asm volatile("cp.async.cg.shared.global [%0], [%1], 16;"
                     :: "r"(bbase + 16u * i), "l"(bsrc + 4 * i));
    }
    asm volatile("cp.async.commit_group;");
}

__global__ __launch_bounds__(256, 2)
void gatesx_kernel(const int* __restrict__ x, const float* __restrict__ h0) {
    extern __shared__ float sg[];

    int tid  = threadIdx.x;
    int warp = tid >> 5;
    int wm   = warp >> 2;
    int wn   = warp & 3;
    int m0   = blockIdx.y * 128;
    int n0   = blockIdx.x * 128;

    if (blockIdx.x == 0 && blockIdx.y == 0) {
        const float4* src = (const float4*)h0;
        float4* dst = (float4*)g_h[0];
        for (int i = tid; i < BB * HH / 4; i += 256) dst[i] = src[i];
        if (tid == 0) g_bar = 0u;
    }

    int r  = tid >> 1;
    int hf = (tid & 1) * 16;

    int sb = m0 + r;
    int s  = sb >> 6;
    int b  = sb & 63;
    const float* arow = g_embT + (size_t)x[b * SS + s] * HH;
    const float* brow = g_wihT + (size_t)(n0 + r) * HH;

    unsigned int sgb = (unsigned int)__cvta_generic_to_shared(sg);

    wmma::fragment<wmma::accumulator, 16, 16, 8, float> acc[4][2];
    #pragma unroll
    for (int mi = 0; mi < 4; mi++)
        #pragma unroll
        for (int ni = 0; ni < 2; ni++) wmma::fill_fragment(acc[mi][ni], 0.0f);

    gx_stage(sgb, arow, brow, r, hf, 0);

    for (int c = 0; c < 32; ++c) {
        asm volatile("cp.async.wait_group 0;");
        __syncthreads();
        if (c + 1 < 32) gx_stage(sgb, arow, brow, r, hf, c + 1);

        const float* As = sg + (c & 1) * GX_STG;
        const float* Bs = As + GX_TILE;
        #pragma unroll
        for (int kk = 0; kk < 32; kk += 8) {
            wmma::fragment<wmma::matrix_a, 16, 16, 8, wmma::precision::tf32, wmma::row_major> af[4];
            wmma::fragment<wmma::matrix_b, 16, 16, 8, wmma::precision::tf32, wmma::col_major> bf[2];
            #pragma unroll
            for (int mi = 0; mi < 4; mi++)
                wmma::load_matrix_sync(af[mi], As + (wm * 64 + mi * 16) * GX_TS + kk, GX_TS);
            #pragma unroll
            for (int ni = 0; ni < 2; ni++)
                wmma::load_matrix_sync(bf[ni], Bs + (wn * 32 + ni * 16) * GX_TS + kk, GX_TS);
            #pragma unroll
            for (int mi = 0; mi < 4; mi++)
                #pragma unroll
                for (int ni = 0; ni < 2; ni++)
                    wmma::mma_sync(acc[mi][ni], af[mi], bf[ni], acc[mi][ni]);
        }
        __syncthreads();
    }

    #pragma unroll
    for (int mi = 0; mi < 4; mi++)
        #pragma unroll
        for (int ni = 0; ni < 2; ni++) {
            float* cp = g_gatesx + (size_t)(m0 + wm * 64 + mi * 16) * GG
                        + n0 + wn * 32 + ni * 16;
            wmma::store_matrix_sync(cp, acc[mi][ni], GG, wmma::mem_row_major);
        }
}

// ---------------------------------------------------------------------------
// Phase B persistent kernel.
// R16: 128-col chunks (8 sync phases/step instead of 16), and the grid
// barrier is the CG-canonical cumulative-release pattern with a SLEEPLESS
// acquire spin (no per-thread threadfence, no nanosleep).
// ---------------------------------------------------------------------------
#define WS_STRIDE 1028
#define CH_STRIDE 132
#define CHUNK_F   (64 * CH_STRIDE)
#define NCH       8
#define SMEM_PERSIST ((32 * WS_STRIDE + 2 * CHUNK_F + 32 + 512 + 4) * 4)

__device__ __forceinline__ float fsig(float x) {
    return __fdividef(1.0f, 1.0f + __expf(-x));
}
__device__ __forceinline__ float ftanh(float x) {
    return 1.0f - __fdividef(2.0f, __expf(2.0f * x) + 1.0f);
}

__device__ __forceinline__ void stage_chunk(unsigned int hs_base,
                                            const float* __restrict__ hin,
                                            int r, int seg, int c) {
    const float* src = hin + (size_t)r * HH + c * 128 + seg * 32;
    unsigned int d = hs_base + (unsigned int)((c & 1) * CHUNK_F + r * CH_STRIDE + seg * 32) * 4u;
    #pragma unroll
    for (int i = 0; i < 8; i++)
        asm volatile("cp.async.cg.shared.global [%0], [%1], 16;"
                     :: "r"(d + 16u * i), "l"(src + 4 * i));
    asm volatile("cp.async.commit_group;");
}

__global__ __launch_bounds__(256, 1)
void lstm_persist(const float* __restrict__ Whh, const float* __restrict__ bih,
                  const float* __restrict__ bhh, const float* __restrict__ c0,
                  const float* __restrict__ fcW, const float* __restrict__ fcb,
                  float* __restrict__ out) {
    extern __shared__ float sm[];
    float* Ws    = sm;                          // [32][1028] tf32 W slice
    float* Hs    = Ws + 32 * WS_STRIDE;         // [2][64][132] h chunks
    float* Gpart = Hs;                          // aliased: [8][64*32] partials
    float* bsum  = Hs + 2 * CHUNK_F;            // [32]
    float* cst   = bsum + 32;                   // [512] private c state
    float* flag  = cst + 512;                   // [1] starvation flag

    int tid  = threadIdx.x;
    int warp = tid >> 5;    // K-slice id (0..7): cols [warp*16, warp*16+16) of each chunk
    int lane = tid & 31;
    int j0   = blockIdx.x * 8;

    unsigned int hs_base = (unsigned int)__cvta_generic_to_shared(Hs);

    for (int i = tid; i < 32 * 256; i += 256) {
        int r  = i >> 8;
        int k4 = (i & 255) << 2;
        float4 v = *(const float4*)(Whh + (size_t)((r >> 3) * HH + j0 + (r & 7)) * HH + k4);
        float* d = Ws + r * WS_STRIDE + k4;
        d[0] = wmma::__float_to_tf32(v.x);
        d[1] = wmma::__float_to_tf32(v.y);
        d[2] = wmma::__float_to_tf32(v.z);
        d[3] = wmma::__float_to_tf32(v.w);
    }
    if (tid < 32) {
        int col = (tid >> 3) * HH + j0 + (tid & 7);
        bsum[tid] = bih[col] + bhh[col];
    }
    if (tid == 0) flag[0] = 0.0f;
    for (int i = tid; i < 512; i += 256) {
        cst[i] = c0[(i >> 3) * HH + j0 + (i & 7)];
    }
    __syncthreads();

    int r   = tid >> 2;         // h row this thread stages (0..63)
    int seg = tid & 3;          // 32-col segment within the 128-col chunk

    bool alive = true;

    for (int s = 0; s < SS && alive; ++s) {
        const float* hin  = g_h[s & 1];
        float*       hout = g_h[(s & 1) ^ 1];

        // Hoist gates_x loads (DRAM latency hides behind the GEMM)
        float gxa[2][4];
        const float* gx = g_gatesx + (size_t)s * BB * GG;
        #pragma unroll
        for (int ii = 0; ii < 2; ii++) {
            int cell = tid + ii * 256;
            const float* gxm = gx + (size_t)(cell >> 3) * GG + j0 + (cell & 7);
            #pragma unroll
            for (int g = 0; g < 4; g++) gxa[ii][g] = __ldcs(gxm + g * HH);
        }

        stage_chunk(hs_base, hin, r, seg, 0);

        wmma::fragment<wmma::accumulator, 16, 16, 8, float> acc[4][2];
        #pragma unroll
        for (int mi = 0; mi < 4; mi++)
            #pragma unroll
            for (int ni = 0; ni < 2; ni++) wmma::fill_fragment(acc[mi][ni], 0.0f);

        int kks = warp * 16;   // this warp's K-offset within each 128-chunk

        for (int c = 0; c < NCH; ++c) {
            asm volatile("cp.async.wait_group 0;");
            __syncthreads();
            if (c + 1 < NCH) stage_chunk(hs_base, hin, r, seg, c + 1);

            const float* hb = Hs + (c & 1) * CHUNK_F + kks;
            const float* wb = Ws + c * 128 + kks;

            #pragma unroll
            for (int k2 = 0; k2 < 16; k2 += 8) {
                wmma::fragment<wmma::matrix_a, 16, 16, 8, wmma::precision::tf32, wmma::row_major> af[4];
                wmma::fragment<wmma::matrix_b, 16, 16, 8, wmma::precision::tf32, wmma::col_major> bf[2];
                #pragma unroll
                for (int mi = 0; mi < 4; mi++)
                    wmma::load_matrix_sync(af[mi], hb + (mi * 16) * CH_STRIDE + k2, CH_STRIDE);
                #pragma unroll
                for (int ni = 0; ni < 2; ni++)
                    wmma::load_matrix_sync(bf[ni], wb + (ni * 16) * WS_STRIDE + k2, WS_STRIDE);
                #pragma unroll
                for (int mi = 0; mi < 4; mi++)
                    #pragma unroll
                    for (int ni = 0; ni < 2; ni++)
                        wmma::mma_sync(acc[mi][ni], af[mi], bf[ni], acc[mi][ni]);
            }
        }
        __syncthreads();   // all warps done reading Hs before Gpart overwrites it

        float* gp = Gpart + warp * (64 * 32);
        #pragma unroll
        for (int mi = 0; mi < 4; mi++)
            #pragma unroll
            for (int ni = 0; ni < 2; ni++)
                wmma::store_matrix_sync(gp + (mi * 16) * 32 + ni * 16, acc[mi][ni], 32,
                                        wmma::mem_row_major);
        __syncthreads();

        #pragma unroll
        for (int ii = 0; ii < 2; ii++) {
            int cell = tid + ii * 256;
            int m = cell >> 3;
            int u = cell & 7;
            float pre[4];
            #pragma unroll
            for (int g = 0; g < 4; g++) pre[g] = gxa[ii][g] + bsum[g * 8 + u];
            #pragma unroll
            for (int w = 0; w < 8; w++) {
                const float* p = Gpart + w * (64 * 32) + m * 32 + u;
                #pragma unroll
                for (int g = 0; g < 4; g++) pre[g] += p[g * 8];
            }
            float ig = fsig(pre[0]);
            float fg = fsig(pre[1]);
            float gg = ftanh(pre[2]);
            float og = fsig(pre[3]);
            float cc = fg * cst[cell] + ig * gg;
            cst[cell] = cc;
            hout[m * HH + j0 + u] = og * ftanh(cc);
        }

        // Grid barrier — CG-canonical: syncthreads (CTA fence, happens-before
        // into tid0) -> cumulative release add -> SLEEPLESS acquire spin.
        __syncthreads();
        if (tid == 0) {
            asm volatile("red.release.gpu.global.add.u32 [%0], %1;"
                         :: "l"(&g_bar), "r"(1u) : "memory");
            unsigned target = (unsigned)(s + 1) * NB;
            unsigned v;
            long long guard = 0;
            while (true) {
                asm volatile("ld.acquire.gpu.global.u32 %0, [%1];"
                             : "=r"(v) : "l"(&g_bar) : "memory");
                if (v >= target) break;
                if (++guard > (1ll << 24)) { flag[0] = 1.0f; break; }
            }
        }
        __syncthreads();
        if (flag[0] != 0.0f) alive = false;
        __syncthreads();
    }

    // fc epilogue: h_last in g_h[0]
    int gw = blockIdx.x * 8 + warp;
    for (int i = gw; i < BB * OO; i += NB * 8) {
        int b = i >> 7;
        int o = i & 127;
        const float* hb = g_h[0] + (size_t)b * HH;
        const float* wo = fcW + (size_t)o * HH;
        float sum = 0.0f;
        for (int k = lane; k < HH; k += 32) sum += __ldcg(hb + k) * wo[k];
        #pragma unroll
        for (int d = 16; d; d >>= 1) sum += __shfl_down_sync(0xffffffffu, sum, d);
        if (lane == 0) out[i] = sum + fcb[o];
    }
}

// ---------------------------------------------------------------------------
extern "C" void kernel_launch(void* const* d_in, const int* in_sizes, int n_in,
                              void* d_out, int out_size) {
    const int*   x   = (const int*)  d_in[0];
    const float* emb = (const float*)d_in[1];
    const float* Wih = (const float*)d_in[2];
    const float* Whh = (const float*)d_in[3];
    const float* bih = (const float*)d_in[4];
    const float* bhh = (const float*)d_in[5];
    const float* fcW = (const float*)d_in[6];
    const float* fcb = (const float*)d_in[7];
    const float* h0  = (const float*)d_in[8];
    const float* c0  = (const float*)d_in[9];
    float* out = (float*)d_out;

    preconvert<<<2048, 256>>>(emb, Wih);
    cudaFuncSetAttribute(gatesx_kernel, cudaFuncAttributeMaxDynamicSharedMemorySize,
                         SMEM_GX);
    gatesx_kernel<<<dim3(32, 512), 256, SMEM_GX>>>(x, h0);
    cudaFuncSetAttribute(lstm_persist, cudaFuncAttributeMaxDynamicSharedMemorySize,
                         SMEM_PERSIST);
    lstm_persist<<<NB, 256, SMEM_PERSIST>>>(Whh, bih, bhh, c0, fcW, fcb, out);
}

// round 17
// speedup vs baseline: 1.0352x; 1.0352x over previous
#include <cuda_runtime.h>
#include <mma.h>
#include <math.h>
#include <cstdint>

using namespace nvcuda;

#define BB 64
#define SS 1024
#define HH 1024
#define GG 4096
#define OO 128
#define NB 128
#define VV 32000

// Scratch (allocation-free rule: __device__ globals)
__device__ float g_gatesx[(size_t)SS * BB * GG];  // [S][B][4H], 1 GiB
__device__ float g_embT[(size_t)VV * HH];         // tf32-RN preconverted emb
__device__ float g_wihT[(size_t)GG * HH];         // tf32-RN preconverted W_ih
__device__ float g_h[2][BB * HH];                 // double-buffered hidden state
__device__ unsigned g_bar;                        // cumulative grid-barrier counter

// ---------------------------------------------------------------------------
// Launch-slot shim: shifts the ncu capture slot so lstm_persist (index 3) is
// profiled. Also (redundantly) clears the barrier counter.
// ---------------------------------------------------------------------------
__global__ void slot_shim() {
    if (threadIdx.x == 0 && blockIdx.x == 0) g_bar = 0u;
}

// ---------------------------------------------------------------------------
__global__ void preconvert(const float* __restrict__ emb,
                           const float* __restrict__ Wih) {
    size_t i0 = (size_t)blockIdx.x * blockDim.x + threadIdx.x;
    size_t stride = (size_t)gridDim.x * blockDim.x;
    for (size_t k = i0; k < (size_t)VV * HH; k += stride)
        g_embT[k] = wmma::__float_to_tf32(emb[k]);
    for (size_t k = i0; k < (size_t)GG * HH; k += stride)
        g_wihT[k] = wmma::__float_to_tf32(Wih[k]);
}

// ---------------------------------------------------------------------------
// Phase A (unchanged from R14): 128x128x32 tiles, cp.async 2-stage, 2 CTA/SM
// ---------------------------------------------------------------------------
#define GX_TS   36
#define GX_TILE (128 * GX_TS)
#define GX_STG  (2 * GX_TILE)
#define SMEM_GX (2 * GX_STG * 4)

__device__ __forceinline__ void gx_stage(unsigned int sgb,
                                         const float* __restrict__ arow,
                                         const float* __restrict__ brow,
                                         int r, int hf, int kt) {
    unsigned int abase = sgb + (unsigned int)((kt & 1) * GX_STG + r * GX_TS + hf) * 4u;
    unsigned int bbase = abase + (unsigned int)GX_TILE * 4u;
    const float* asrc = arow + kt * 32 + hf;
    const float* bsrc = brow + kt * 32 + hf;
    #pragma unroll
    for (int i = 0; i < 4; i++) {
        asm volatile("cp.async.cg.shared.global [%0], [%1], 16;"
                     :: "r"(abase + 16u * i), "l"(asrc + 4 * i));
        asm volatile("cp.async.cg.shared.global [%0], [%1], 16;"
                     :: "r"(bbase + 16u * i), "l"(bsrc + 4 * i));
    }
    asm volatile("cp.async.commit_group;");
}

__global__ __launch_bounds__(256, 2)
void gatesx_kernel(const int* __restrict__ x, const float* __restrict__ h0) {
    extern __shared__ float sg[];

    int tid  = threadIdx.x;
    int warp = tid >> 5;
    int wm   = warp >> 2;
    int wn   = warp & 3;
    int m0   = blockIdx.y * 128;
    int n0   = blockIdx.x * 128;

    if (blockIdx.x == 0 && blockIdx.y == 0) {
        const float4* src = (const float4*)h0;
        float4* dst = (float4*)g_h[0];
        for (int i = tid; i < BB * HH / 4; i += 256) dst[i] = src[i];
        if (tid == 0) g_bar = 0u;
    }

    int r  = tid >> 1;
    int hf = (tid & 1) * 16;

    int sb = m0 + r;
    int s  = sb >> 6;
    int b  = sb & 63;
    const float* arow = g_embT + (size_t)x[b * SS + s] * HH;
    const float* brow = g_wihT + (size_t)(n0 + r) * HH;

    unsigned int sgb = (unsigned int)__cvta_generic_to_shared(sg);

    wmma::fragment<wmma::accumulator, 16, 16, 8, float> acc[4][2];
    #pragma unroll
    for (int mi = 0; mi < 4; mi++)
        #pragma unroll
        for (int ni = 0; ni < 2; ni++) wmma::fill_fragment(acc[mi][ni], 0.0f);

    gx_stage(sgb, arow, brow, r, hf, 0);

    for (int c = 0; c < 32; ++c) {
        asm volatile("cp.async.wait_group 0;");
        __syncthreads();
        if (c + 1 < 32) gx_stage(sgb, arow, brow, r, hf, c + 1);

        const float* As = sg + (c & 1) * GX_STG;
        const float* Bs = As + GX_TILE;
        #pragma unroll
        for (int kk = 0; kk < 32; kk += 8) {
            wmma::fragment<wmma::matrix_a, 16, 16, 8, wmma::precision::tf32, wmma::row_major> af[4];
            wmma::fragment<wmma::matrix_b, 16, 16, 8, wmma::precision::tf32, wmma::col_major> bf[2];
            #pragma unroll
            for (int mi = 0; mi < 4; mi++)
                wmma::load_matrix_sync(af[mi], As + (wm * 64 + mi * 16) * GX_TS + kk, GX_TS);
            #pragma unroll
            for (int ni = 0; ni < 2; ni++)
                wmma::load_matrix_sync(bf[ni], Bs + (wn * 32 + ni * 16) * GX_TS + kk, GX_TS);
            #pragma unroll
            for (int mi = 0; mi < 4; mi++)
                #pragma unroll
                for (int ni = 0; ni < 2; ni++)
                    wmma::mma_sync(acc[mi][ni], af[mi], bf[ni], acc[mi][ni]);
        }
        __syncthreads();
    }

    #pragma unroll
    for (int mi = 0; mi < 4; mi++)
        #pragma unroll
        for (int ni = 0; ni < 2; ni++) {
            float* cp = g_gatesx + (size_t)(m0 + wm * 64 + mi * 16) * GG
                        + n0 + wn * 32 + ni * 16;
            wmma::store_matrix_sync(cp, acc[mi][ni], GG, wmma::mem_row_major);
        }
}

// ---------------------------------------------------------------------------
// Phase B persistent kernel — R14 structure, but W tile at ODD stride 1033:
// (n*1033 + k) mod 32 is collision-free for any fragment lane pattern, so
// B-fragment LDS bank conflicts are impossible. W staged with scalar stores
// (once per kernel; cost irrelevant).
// ---------------------------------------------------------------------------
#define WS_STRIDE 1033
#define CH_STRIDE 68
#define CHUNK_F   (64 * CH_STRIDE)
#define NPIPE     4
#define NCH       16
#define SMEM_PERSIST ((32 * WS_STRIDE + NPIPE * CHUNK_F + 32 + 512 + 4) * 4)

__device__ __forceinline__ float fsig(float x) {
    return __fdividef(1.0f, 1.0f + __expf(-x));
}
__device__ __forceinline__ float ftanh(float x) {
    return 1.0f - __fdividef(2.0f, __expf(2.0f * x) + 1.0f);
}

__device__ __forceinline__ void stage_chunk(unsigned int hs_base,
                                            const float* __restrict__ hin,
                                            int hrow, int hc16, int c) {
    const float* src = hin + (size_t)hrow * HH + c * 64 + hc16;
    unsigned int d = hs_base + (unsigned int)((c & 3) * CHUNK_F + hrow * CH_STRIDE + hc16) * 4u;
    #pragma unroll
    for (int i = 0; i < 4; i++)
        asm volatile("cp.async.cg.shared.global [%0], [%1], 16;"
                     :: "r"(d + 16u * i), "l"(src + 4 * i));
    asm volatile("cp.async.commit_group;");
}

__global__ __launch_bounds__(256, 1)
void lstm_persist(const float* __restrict__ Whh, const float* __restrict__ bih,
                  const float* __restrict__ bhh, const float* __restrict__ c0,
                  const float* __restrict__ fcW, const float* __restrict__ fcb,
                  float* __restrict__ out) {
    extern __shared__ float sm[];
    float* Ws    = sm;                          // [32][1033] tf32 W slice (odd stride)
    float* Hs    = Ws + 32 * WS_STRIDE;         // [NPIPE][64][68] h chunks
    float* Gpart = Hs;                          // aliased: [8][64*32] partials
    float* bsum  = Hs + NPIPE * CHUNK_F;        // [32]
    float* cst   = bsum + 32;                   // [512] private c state
    float* flag  = cst + 512;                   // [1] starvation flag

    int tid  = threadIdx.x;
    int warp = tid >> 5;    // K-slice id (0..7)
    int lane = tid & 31;
    int j0   = blockIdx.x * 8;

    unsigned int hs_base = (unsigned int)__cvta_generic_to_shared(Hs);

    // W slice staged with SCALAR stores (coalesced reads; once per kernel)
    for (int idx = tid; idx < 32 * 1024; idx += 256) {
        int r = idx >> 10;
        int k = idx & 1023;
        float v = Whh[(size_t)((r >> 3) * HH + j0 + (r & 7)) * HH + k];
        Ws[r * WS_STRIDE + k] = wmma::__float_to_tf32(v);
    }
    if (tid < 32) {
        int col = (tid >> 3) * HH + j0 + (tid & 7);
        bsum[tid] = bih[col] + bhh[col];
    }
    if (tid == 0) flag[0] = 0.0f;
    for (int i = tid; i < 512; i += 256) {
        cst[i] = c0[(i >> 3) * HH + j0 + (i & 7)];
    }
    __syncthreads();

    int hrow = tid >> 2;
    int hc16 = (tid & 3) << 4;

    bool alive = true;

    for (int s = 0; s < SS && alive; ++s) {
        const float* hin  = g_h[s & 1];
        float*       hout = g_h[(s & 1) ^ 1];

        // Hoist gates_x loads (DRAM latency hides behind the GEMM)
        float gxa[2][4];
        const float* gx = g_gatesx + (size_t)s * BB * GG;
        #pragma unroll
        for (int ii = 0; ii < 2; ii++) {
            int cell = tid + ii * 256;
            const float* gxm = gx + (size_t)(cell >> 3) * GG + j0 + (cell & 7);
            #pragma unroll
            for (int g = 0; g < 4; g++) gxa[ii][g] = __ldcs(gxm + g * HH);
        }

        #pragma unroll
        for (int c = 0; c < NPIPE - 1; c++) stage_chunk(hs_base, hin, hrow, hc16, c);

        wmma::fragment<wmma::accumulator, 16, 16, 8, float> acc[4][2];
        #pragma unroll
        for (int mi = 0; mi < 4; mi++)
            #pragma unroll
            for (int ni = 0; ni < 2; ni++) wmma::fill_fragment(acc[mi][ni], 0.0f);

        int kks = warp * 8;

        for (int c = 0; c < NCH; ++c) {
            asm volatile("cp.async.wait_group %0;" :: "n"(NPIPE - 2));
            __syncthreads();
            if (c + NPIPE - 1 < NCH) stage_chunk(hs_base, hin, hrow, hc16, c + NPIPE - 1);
            const float* hb = Hs + (c & 3) * CHUNK_F + kks;
            const float* wb = Ws + c * 64 + kks;

            wmma::fragment<wmma::matrix_a, 16, 16, 8, wmma::precision::tf32, wmma::row_major> af[4];
            wmma::fragment<wmma::matrix_b, 16, 16, 8, wmma::precision::tf32, wmma::col_major> bf[2];
            #pragma unroll
            for (int mi = 0; mi < 4; mi++)
                wmma::load_matrix_sync(af[mi], hb + (mi * 16) * CH_STRIDE, CH_STRIDE);
            #pragma unroll
            for (int ni = 0; ni < 2; ni++)
                wmma::load_matrix_sync(bf[ni], wb + (ni * 16) * WS_STRIDE, WS_STRIDE);
            #pragma unroll
            for (int mi = 0; mi < 4; mi++)
                #pragma unroll
                for (int ni = 0; ni < 2; ni++)
                    wmma::mma_sync(acc[mi][ni], af[mi], bf[ni], acc[mi][ni]);
        }
        asm volatile("cp.async.wait_group 0;");
        __syncthreads();

        float* gp = Gpart + warp * (64 * 32);
        #pragma unroll
        for (int mi = 0; mi < 4; mi++)
            #pragma unroll
            for (int ni = 0; ni < 2; ni++)
                wmma::store_matrix_sync(gp + (mi * 16) * 32 + ni * 16, acc[mi][ni], 32,
                                        wmma::mem_row_major);
        __syncthreads();

        #pragma unroll
        for (int ii = 0; ii < 2; ii++) {
            int cell = tid + ii * 256;
            int m = cell >> 3;
            int u = cell & 7;
            float pre[4];
            #pragma unroll
            for (int g = 0; g < 4; g++) pre[g] = gxa[ii][g] + bsum[g * 8 + u];
            #pragma unroll
            for (int w = 0; w < 8; w++) {
                const float* p = Gpart + w * (64 * 32) + m * 32 + u;
                #pragma unroll
                for (int g = 0; g < 4; g++) pre[g] += p[g * 8];
            }
            float ig = fsig(pre[0]);
            float fg = fsig(pre[1]);
            float gg = ftanh(pre[2]);
            float og = fsig(pre[3]);
            float cc = fg * cst[cell] + ig * gg;
            cst[cell] = cc;
            hout[m * HH + j0 + u] = og * ftanh(cc);
        }

        // Grid barrier (R3-proven sequence) + bounded spin
        __threadfence();
        __syncthreads();
        if (tid == 0) {
            atomicAdd(&g_bar, 1u);
            unsigned target = (unsigned)(s + 1) * NB;
            long long guard = 0;
            while (*(volatile unsigned*)&g_bar < target) {
                __nanosleep(64);
                if (++guard > (64ll << 20)) { g_bar = 0xC0000000u; break; }
            }
            if (*(volatile unsigned*)&g_bar >= 0xC0000000u) flag[0] = 1.0f;
        }
        __syncthreads();
        if (flag[0] != 0.0f) alive = false;
        __syncthreads();
    }

    // fc epilogue: h_last in g_h[0]
    int gw = blockIdx.x * 8 + warp;
    for (int i = gw; i < BB * OO; i += NB * 8) {
        int b = i >> 7;
        int o = i & 127;
        const float* hb = g_h[0] + (size_t)b * HH;
        const float* wo = fcW + (size_t)o * HH;
        float sum = 0.0f;
        for (int k = lane; k < HH; k += 32) sum += __ldcg(hb + k) * wo[k];
        #pragma unroll
        for (int d = 16; d; d >>= 1) sum += __shfl_down_sync(0xffffffffu, sum, d);
        if (lane == 0) out[i] = sum + fcb[o];
    }
}

// ---------------------------------------------------------------------------
extern "C" void kernel_launch(void* const* d_in, const int* in_sizes, int n_in,
                              void* d_out, int out_size) {
    const int*   x   = (const int*)  d_in[0];
    const float* emb = (const float*)d_in[1];
    const float* Wih = (const float*)d_in[2];
    const float* Whh = (const float*)d_in[3];
    const float* bih = (const float*)d_in[4];
    const float* bhh = (const float*)d_in[5];
    const float* fcW = (const float*)d_in[6];
    const float* fcb = (const float*)d_in[7];
    const float* h0  = (const float*)d_in[8];
    const float* c0  = (const float*)d_in[9];
    float* out = (float*)d_out;

    slot_shim<<<1, 32>>>();
    preconvert<<<2048, 256>>>(emb, Wih);
    cudaFuncSetAttribute(gatesx_kernel, cudaFuncAttributeMaxDynamicSharedMemorySize,
                         SMEM_GX);
    gatesx_kernel<<<dim3(32, 512), 256, SMEM_GX>>>(x, h0);
    cudaFuncSetAttribute(lstm_persist, cudaFuncAttributeMaxDynamicSharedMemorySize,
                         SMEM_PERSIST);
    lstm_persist<<<NB, 256, SMEM_PERSIST>>>(Whh, bih, bhh, c0, fcW, fcb, out);
}